// round 3
// baseline (speedup 1.0000x reference)
#include <cuda_runtime.h>
#include <math.h>

// Router: logits = x @ W^T  (M=16384 tokens, N=64 experts, K=4096 hidden, fp32)
// then per-token top-2 + softmax over the 2 selected logits.
// Output layout (out_size = 65536 floats):
//   [0 .. 2*TOKENS)          : softmax weights, row-major [token][2]
//   [2*TOKENS .. 4*TOKENS)   : selected expert indices as float, [token][2]

constexpr int TOKENS = 16384;
constexpr int HIDDEN = 4096;
constexpr int NEXP   = 64;

constexpr int TM = 64;   // tokens per block
constexpr int KC = 32;   // K chunk
constexpr int XS_STRIDE = TM + 4;    // 68 floats: 16B-aligned rows, conflict-spread
constexpr int WS_STRIDE = NEXP + 4;  // 68

__global__ __launch_bounds__(256) void router_kernel(
    const float* __restrict__ x,
    const float* __restrict__ w,
    float* __restrict__ out)
{
    __shared__ float xs[KC][XS_STRIDE];   // transposed: xs[k][token]
    __shared__ float ws[KC][WS_STRIDE];   // transposed: ws[k][expert]
    __shared__ float lg[TM][NEXP + 1];    // logits for epilogue

    const int tid = threadIdx.x;
    const int t0  = blockIdx.x * TM;

    // compute mapping: 16x16 thread grid, each thread -> 4 tokens x 4 experts
    const int tx = tid & 15;   // expert group
    const int ty = tid >> 4;   // token group

    float acc[4][4] = {};

    // load mapping: each thread loads 2 rows (lt, lt+32), 4 consecutive k (lc..lc+3)
    const int lt = tid >> 3;          // 0..31
    const int lc = (tid & 7) << 2;    // 0,4,...,28

    const float* xp0 = x + (size_t)(t0 + lt)      * HIDDEN + lc;
    const float* xp1 = x + (size_t)(t0 + lt + 32) * HIDDEN + lc;
    const float* wp0 = w + (size_t)lt        * HIDDEN + lc;
    const float* wp1 = w + (size_t)(lt + 32) * HIDDEN + lc;

    for (int k0 = 0; k0 < HIDDEN; k0 += KC) {
        const float4 xv0 = *(const float4*)(xp0 + k0);
        const float4 xv1 = *(const float4*)(xp1 + k0);
        const float4 wv0 = *(const float4*)(wp0 + k0);
        const float4 wv1 = *(const float4*)(wp1 + k0);

        __syncthreads();  // previous chunk fully consumed before overwrite

        xs[lc+0][lt]    = xv0.x; xs[lc+1][lt]    = xv0.y;
        xs[lc+2][lt]    = xv0.z; xs[lc+3][lt]    = xv0.w;
        xs[lc+0][lt+32] = xv1.x; xs[lc+1][lt+32] = xv1.y;
        xs[lc+2][lt+32] = xv1.z; xs[lc+3][lt+32] = xv1.w;

        ws[lc+0][lt]    = wv0.x; ws[lc+1][lt]    = wv0.y;
        ws[lc+2][lt]    = wv0.z; ws[lc+3][lt]    = wv0.w;
        ws[lc+0][lt+32] = wv1.x; ws[lc+1][lt+32] = wv1.y;
        ws[lc+2][lt+32] = wv1.z; ws[lc+3][lt+32] = wv1.w;

        __syncthreads();

        #pragma unroll
        for (int k = 0; k < KC; ++k) {
            const float4 a = *(const float4*)&xs[k][ty << 2];
            const float4 b = *(const float4*)&ws[k][tx << 2];
            acc[0][0] += a.x * b.x;  acc[0][1] += a.x * b.y;
            acc[0][2] += a.x * b.z;  acc[0][3] += a.x * b.w;
            acc[1][0] += a.y * b.x;  acc[1][1] += a.y * b.y;
            acc[1][2] += a.y * b.z;  acc[1][3] += a.y * b.w;
            acc[2][0] += a.z * b.x;  acc[2][1] += a.z * b.y;
            acc[2][2] += a.z * b.z;  acc[2][3] += a.z * b.w;
            acc[3][0] += a.w * b.x;  acc[3][1] += a.w * b.y;
            acc[3][2] += a.w * b.z;  acc[3][3] += a.w * b.w;
        }
    }

    __syncthreads();
    #pragma unroll
    for (int i = 0; i < 4; ++i)
        #pragma unroll
        for (int j = 0; j < 4; ++j)
            lg[(ty << 2) + i][(tx << 2) + j] = acc[i][j];
    __syncthreads();

    // Epilogue: one thread per token does top-2 + softmax.
    if (tid < TM) {
        float v1 = -INFINITY, v2 = -INFINITY;
        int i1 = 0, i2 = 0;
        #pragma unroll
        for (int e = 0; e < NEXP; ++e) {
            const float v = lg[tid][e];
            if (v > v1) { v2 = v1; i2 = i1; v1 = v; i1 = e; }
            else if (v > v2) { v2 = v; i2 = e; }
        }
        // softmax over [v1, v2] (v1 >= v2, numerically safe)
        const float e2  = expf(v2 - v1);
        const float inv = 1.0f / (1.0f + e2);
        const int t = t0 + tid;
        out[2 * t + 0] = inv;         // weight of top-1
        out[2 * t + 1] = e2 * inv;    // weight of top-2
        out[2 * TOKENS + 2 * t + 0] = (float)i1;
        out[2 * TOKENS + 2 * t + 1] = (float)i2;
    }
}

extern "C" void kernel_launch(void* const* d_in, const int* in_sizes, int n_in,
                              void* d_out, int out_size) {
    const float* x = (const float*)d_in[0];      // [TOKENS, HIDDEN]
    const float* w = (const float*)d_in[1];      // [NEXP, HIDDEN]
    float* out = (float*)d_out;
    router_kernel<<<TOKENS / TM, 256>>>(x, w, out);
}

// round 6
// speedup vs baseline: 1.0051x; 1.0051x over previous
#include <cuda_runtime.h>
#include <math.h>

// Router: logits = x @ W^T  (M=16384 tokens, N=64 experts, K=4096 hidden, fp32)
// then per-token top-2 + softmax over the 2 selected logits.
// Output layout (out_size = 65536 floats):
//   [0 .. 2*TOKENS)          : softmax weights, row-major [token][2]
//   [2*TOKENS .. 4*TOKENS)   : selected expert indices as float, [token][2]

constexpr int TOKENS = 16384;
constexpr int HIDDEN = 4096;
constexpr int NEXP   = 64;

constexpr int TM = 64;   // tokens per block
constexpr int KC = 32;   // K chunk
constexpr int XS_STRIDE = TM + 4;    // 68 floats: 16B-aligned rows, conflict-spread
constexpr int WS_STRIDE = NEXP + 4;  // 68

__global__ __launch_bounds__(256) void router_kernel(
    const float* __restrict__ x,
    const float* __restrict__ w,
    float* __restrict__ out)
{
    __shared__ float xs[KC][XS_STRIDE];   // transposed: xs[k][token]
    __shared__ float ws[KC][WS_STRIDE];   // transposed: ws[k][expert]
    __shared__ float lg[TM][NEXP + 1];    // logits for epilogue

    const int tid = threadIdx.x;
    const int t0  = blockIdx.x * TM;

    // compute mapping: 16x16 thread grid, each thread -> 4 tokens x 4 experts
    const int tx = tid & 15;   // expert group
    const int ty = tid >> 4;   // token group

    float acc[4][4] = {};

    // load mapping: each thread loads 2 rows (lt, lt+32), 4 consecutive k (lc..lc+3)
    const int lt = tid >> 3;          // 0..31
    const int lc = (tid & 7) << 2;    // 0,4,...,28

    const float* xp0 = x + (size_t)(t0 + lt)      * HIDDEN + lc;
    const float* xp1 = x + (size_t)(t0 + lt + 32) * HIDDEN + lc;
    const float* wp0 = w + (size_t)lt        * HIDDEN + lc;
    const float* wp1 = w + (size_t)(lt + 32) * HIDDEN + lc;

    for (int k0 = 0; k0 < HIDDEN; k0 += KC) {
        const float4 xv0 = *(const float4*)(xp0 + k0);
        const float4 xv1 = *(const float4*)(xp1 + k0);
        const float4 wv0 = *(const float4*)(wp0 + k0);
        const float4 wv1 = *(const float4*)(wp1 + k0);

        __syncthreads();  // previous chunk fully consumed before overwrite

        xs[lc+0][lt]    = xv0.x; xs[lc+1][lt]    = xv0.y;
        xs[lc+2][lt]    = xv0.z; xs[lc+3][lt]    = xv0.w;
        xs[lc+0][lt+32] = xv1.x; xs[lc+1][lt+32] = xv1.y;
        xs[lc+2][lt+32] = xv1.z; xs[lc+3][lt+32] = xv1.w;

        ws[lc+0][lt]    = wv0.x; ws[lc+1][lt]    = wv0.y;
        ws[lc+2][lt]    = wv0.z; ws[lc+3][lt]    = wv0.w;
        ws[lc+0][lt+32] = wv1.x; ws[lc+1][lt+32] = wv1.y;
        ws[lc+2][lt+32] = wv1.z; ws[lc+3][lt+32] = wv1.w;

        __syncthreads();

        #pragma unroll
        for (int k = 0; k < KC; ++k) {
            const float4 a = *(const float4*)&xs[k][ty << 2];
            const float4 b = *(const float4*)&ws[k][tx << 2];
            acc[0][0] += a.x * b.x;  acc[0][1] += a.x * b.y;
            acc[0][2] += a.x * b.z;  acc[0][3] += a.x * b.w;
            acc[1][0] += a.y * b.x;  acc[1][1] += a.y * b.y;
            acc[1][2] += a.y * b.z;  acc[1][3] += a.y * b.w;
            acc[2][0] += a.z * b.x;  acc[2][1] += a.z * b.y;
            acc[2][2] += a.z * b.z;  acc[2][3] += a.z * b.w;
            acc[3][0] += a.w * b.x;  acc[3][1] += a.w * b.y;
            acc[3][2] += a.w * b.z;  acc[3][3] += a.w * b.w;
        }
    }

    __syncthreads();
    #pragma unroll
    for (int i = 0; i < 4; ++i)
        #pragma unroll
        for (int j = 0; j < 4; ++j)
            lg[(ty << 2) + i][(tx << 2) + j] = acc[i][j];
    __syncthreads();

    // Epilogue: one thread per token does top-2 + softmax.
    if (tid < TM) {
        float v1 = -INFINITY, v2 = -INFINITY;
        int i1 = 0, i2 = 0;
        #pragma unroll
        for (int e = 0; e < NEXP; ++e) {
            const float v = lg[tid][e];
            if (v > v1) { v2 = v1; i2 = i1; v1 = v; i1 = e; }
            else if (v > v2) { v2 = v; i2 = e; }
        }
        // softmax over [v1, v2] (v1 >= v2, numerically safe)
        const float e2  = expf(v2 - v1);
        const float inv = 1.0f / (1.0f + e2);
        const int t = t0 + tid;
        out[2 * t + 0] = inv;         // weight of top-1
        out[2 * t + 1] = e2 * inv;    // weight of top-2
        out[2 * TOKENS + 2 * t + 0] = (float)i1;
        out[2 * TOKENS + 2 * t + 1] = (float)i2;
    }
}

extern "C" void kernel_launch(void* const* d_in, const int* in_sizes, int n_in,
                              void* d_out, int out_size) {
    const float* x = (const float*)d_in[0];      // [TOKENS, HIDDEN]
    const float* w = (const float*)d_in[1];      // [NEXP, HIDDEN]
    float* out = (float*)d_out;
    router_kernel<<<TOKENS / TM, 256>>>(x, w, out);
}

// round 8
// speedup vs baseline: 1.0053x; 1.0002x over previous
#include <cuda_runtime.h>
#include <math.h>

// Router: logits = x @ W^T  (M=16384 tokens, N=64 experts, K=4096 hidden, fp32)
// then per-token top-2 + softmax over the 2 selected logits.
// Output layout (out_size = 65536 floats):
//   [0 .. 2*TOKENS)          : softmax weights, row-major [token][2]
//   [2*TOKENS .. 4*TOKENS)   : selected expert indices as float, [token][2]

constexpr int TOKENS = 16384;
constexpr int HIDDEN = 4096;
constexpr int NEXP   = 64;

constexpr int TM = 64;   // tokens per block
constexpr int KC = 32;   // K chunk
constexpr int XS_STRIDE = TM + 4;    // 68 floats: 16B-aligned rows, conflict-spread
constexpr int WS_STRIDE = NEXP + 4;  // 68

__global__ __launch_bounds__(256) void router_kernel(
    const float* __restrict__ x,
    const float* __restrict__ w,
    float* __restrict__ out)
{
    __shared__ float xs[KC][XS_STRIDE];   // transposed: xs[k][token]
    __shared__ float ws[KC][WS_STRIDE];   // transposed: ws[k][expert]
    __shared__ float lg[TM][NEXP + 1];    // logits for epilogue

    const int tid = threadIdx.x;
    const int t0  = blockIdx.x * TM;

    // compute mapping: 16x16 thread grid, each thread -> 4 tokens x 4 experts
    const int tx = tid & 15;   // expert group
    const int ty = tid >> 4;   // token group

    float acc[4][4] = {};

    // load mapping: each thread loads 2 rows (lt, lt+32), 4 consecutive k (lc..lc+3)
    const int lt = tid >> 3;          // 0..31
    const int lc = (tid & 7) << 2;    // 0,4,...,28

    const float* xp0 = x + (size_t)(t0 + lt)      * HIDDEN + lc;
    const float* xp1 = x + (size_t)(t0 + lt + 32) * HIDDEN + lc;
    const float* wp0 = w + (size_t)lt        * HIDDEN + lc;
    const float* wp1 = w + (size_t)(lt + 32) * HIDDEN + lc;

    for (int k0 = 0; k0 < HIDDEN; k0 += KC) {
        const float4 xv0 = *(const float4*)(xp0 + k0);
        const float4 xv1 = *(const float4*)(xp1 + k0);
        const float4 wv0 = *(const float4*)(wp0 + k0);
        const float4 wv1 = *(const float4*)(wp1 + k0);

        __syncthreads();  // previous chunk fully consumed before overwrite

        xs[lc+0][lt]    = xv0.x; xs[lc+1][lt]    = xv0.y;
        xs[lc+2][lt]    = xv0.z; xs[lc+3][lt]    = xv0.w;
        xs[lc+0][lt+32] = xv1.x; xs[lc+1][lt+32] = xv1.y;
        xs[lc+2][lt+32] = xv1.z; xs[lc+3][lt+32] = xv1.w;

        ws[lc+0][lt]    = wv0.x; ws[lc+1][lt]    = wv0.y;
        ws[lc+2][lt]    = wv0.z; ws[lc+3][lt]    = wv0.w;
        ws[lc+0][lt+32] = wv1.x; ws[lc+1][lt+32] = wv1.y;
        ws[lc+2][lt+32] = wv1.z; ws[lc+3][lt+32] = wv1.w;

        __syncthreads();

        #pragma unroll
        for (int k = 0; k < KC; ++k) {
            const float4 a = *(const float4*)&xs[k][ty << 2];
            const float4 b = *(const float4*)&ws[k][tx << 2];
            acc[0][0] += a.x * b.x;  acc[0][1] += a.x * b.y;
            acc[0][2] += a.x * b.z;  acc[0][3] += a.x * b.w;
            acc[1][0] += a.y * b.x;  acc[1][1] += a.y * b.y;
            acc[1][2] += a.y * b.z;  acc[1][3] += a.y * b.w;
            acc[2][0] += a.z * b.x;  acc[2][1] += a.z * b.y;
            acc[2][2] += a.z * b.z;  acc[2][3] += a.z * b.w;
            acc[3][0] += a.w * b.x;  acc[3][1] += a.w * b.y;
            acc[3][2] += a.w * b.z;  acc[3][3] += a.w * b.w;
        }
    }

    __syncthreads();
    #pragma unroll
    for (int i = 0; i < 4; ++i)
        #pragma unroll
        for (int j = 0; j < 4; ++j)
            lg[(ty << 2) + i][(tx << 2) + j] = acc[i][j];
    __syncthreads();

    // Epilogue: one thread per token does top-2 + softmax.
    if (tid < TM) {
        float v1 = -INFINITY, v2 = -INFINITY;
        int i1 = 0, i2 = 0;
        #pragma unroll
        for (int e = 0; e < NEXP; ++e) {
            const float v = lg[tid][e];
            if (v > v1) { v2 = v1; i2 = i1; v1 = v; i1 = e; }
            else if (v > v2) { v2 = v; i2 = e; }
        }
        // softmax over [v1, v2] (v1 >= v2, numerically safe)
        const float e2  = expf(v2 - v1);
        const float inv = 1.0f / (1.0f + e2);
        const int t = t0 + tid;
        out[2 * t + 0] = inv;         // weight of top-1
        out[2 * t + 1] = e2 * inv;    // weight of top-2
        out[2 * TOKENS + 2 * t + 0] = (float)i1;
        out[2 * TOKENS + 2 * t + 1] = (float)i2;
    }
}

extern "C" void kernel_launch(void* const* d_in, const int* in_sizes, int n_in,
                              void* d_out, int out_size) {
    const float* x = (const float*)d_in[0];      // [TOKENS, HIDDEN]
    const float* w = (const float*)d_in[1];      // [NEXP, HIDDEN]
    float* out = (float*)d_out;
    router_kernel<<<TOKENS / TM, 256>>>(x, w, out);
}